// round 17
// baseline (speedup 1.0000x reference)
#include <cuda_runtime.h>
#include <cuda_bf16.h>
#include <math.h>

#define LL   2048
#define DD   2048
#define HH   16
#define DKK  1024
#define DVV  2048
#define HDKK 64
#define HDVV 128
#define NCAT 6144              // q(1024) | k(1024) | v(2048) | g(2048)

// ---------------- scratch (device globals; no allocation allowed) ----------
__device__ float g_xc  [LL*DD];      // conv+silu output (fp32 exact, for router)
__device__ float g_xctf[LL*DD];      // conv+silu output, tf32-rounded (GEMM A)
__device__ float g_qkvg[LL*NCAT];    // projection output (only g block written)
__device__ float g_w2  [DD*32];      // Wv @ router_w  (fp32 exact)
__device__ float g_rlog[LL*32];      // router logits  (fp32 exact)
__device__ __nv_bfloat16 g_qh[LL*DKK];   // roped q hi, [h][l][64]
__device__ __nv_bfloat16 g_ql[LL*DKK];   // roped q lo
__device__ __nv_bfloat16 g_kh[LL*DKK];   // roped k hi
__device__ __nv_bfloat16 g_kl[LL*DKK];   // roped k lo
__device__ __nv_bfloat16 g_vth[HH*HDVV*LL]; // v hi, TRANSPOSED [h][c][l]
__device__ __nv_bfloat16 g_vtl[HH*HDVV*LL]; // v lo, transposed
__device__ float g_y   [LL*DVV];     // silu(g)*LN(o), tf32-rounded
__device__ float g_coef[HH*LL];      // score_max/count * HDK^-0.5
__device__ int   g_rsel[HH*LL];      // selected expert per (h,l)

__device__ __forceinline__ float silu_f(float z) { return z / (1.f + expf(-z)); }

__device__ __forceinline__ unsigned f2tf(float f) {
    unsigned r;
    asm("cvt.rna.tf32.f32 %0, %1;" : "=r"(r) : "f"(f));
    return r;
}
__device__ __forceinline__ float tf32r(float f) { return __uint_as_float(f2tf(f)); }

__device__ __forceinline__ unsigned f2bfu(float f) {
    return (unsigned)__bfloat16_as_ushort(__float2bfloat16_rn(f));
}
__device__ __forceinline__ float bfu2f(unsigned u) {
    return __bfloat162float(__ushort_as_bfloat16((unsigned short)u));
}
__device__ __forceinline__ void split_bf(float v, unsigned& hi, unsigned& lo) {
    hi = f2bfu(v);
    lo = f2bfu(v - bfu2f(hi));
}

__device__ __forceinline__ void mma8(float* c,
                                     unsigned a0, unsigned a1, unsigned a2, unsigned a3,
                                     unsigned b0, unsigned b1) {
    asm("mma.sync.aligned.m16n8k8.row.col.f32.tf32.tf32.f32 "
        "{%0,%1,%2,%3}, {%4,%5,%6,%7}, {%8,%9}, {%0,%1,%2,%3};"
        : "+f"(c[0]), "+f"(c[1]), "+f"(c[2]), "+f"(c[3])
        : "r"(a0), "r"(a1), "r"(a2), "r"(a3), "r"(b0), "r"(b1));
}

__device__ __forceinline__ void mma16(float* c,
                                      unsigned a0, unsigned a1, unsigned a2, unsigned a3,
                                      unsigned b0, unsigned b1) {
    asm("mma.sync.aligned.m16n8k16.row.col.f32.bf16.bf16.f32 "
        "{%0,%1,%2,%3}, {%4,%5,%6,%7}, {%8,%9}, {%0,%1,%2,%3};"
        : "+f"(c[0]), "+f"(c[1]), "+f"(c[2]), "+f"(c[3])
        : "r"(a0), "r"(a1), "r"(a2), "r"(a3), "r"(b0), "r"(b1));
}

__device__ __forceinline__ void cp16(float* smem_dst, const float* gsrc) {
    unsigned sa = (unsigned)__cvta_generic_to_shared(smem_dst);
    asm volatile("cp.async.cg.shared.global [%0], [%1], 16;\n"
                 :: "r"(sa), "l"(gsrc));
}
__device__ __forceinline__ void cp16b(unsigned* smem_dst, const __nv_bfloat16* gsrc) {
    unsigned sa = (unsigned)__cvta_generic_to_shared(smem_dst);
    asm volatile("cp.async.cg.shared.global [%0], [%1], 16;\n"
                 :: "r"(sa), "l"(gsrc));
}

// ---------------- stage 1: shifted conv + silu, fused with W2 --------------
// blocks [0, LL*DD/256): conv+silu.  blocks >= that: W2 = Wv @ router_w.
#define CONV_BLKS ((LL*DD)/256)

__global__ void conv_silu_kernel(const float* __restrict__ x,
                                 const float* __restrict__ cw,
                                 const float* __restrict__ Wv,
                                 const float* __restrict__ rw) {
    if (blockIdx.x < CONV_BLKS) {
        int idx = blockIdx.x * 256 + threadIdx.x;  // over L*D
        int d = idx & (DD-1);
        int l = idx >> 11;
        float prev = (l == 0) ? 0.f : x[idx - DD];
        float z = prev * cw[2*d] + x[idx] * cw[2*d + 1];
        float v = silu_f(z);
        g_xc[idx]   = v;
        g_xctf[idx] = tf32r(v);
    } else {
        // W2 = Wv @ router_w (fp32 exact, [2048][32]); 256 blocks x 8 k-rows
        int b   = blockIdx.x - CONV_BLKS;
        int tid = threadIdx.x;
        int k  = b * 8 + (tid >> 5);
        int t  = tid & 31;
        int h  = t >> 1, r = t & 1;
        const float* wrow = Wv + (size_t)k * DVV + h * HDVV;
        const float* rr   = rw + (h * HDVV) * 2 + r;
        float a0 = 0.f, a1 = 0.f, a2 = 0.f, a3 = 0.f;
        #pragma unroll 8
        for (int d = 0; d < HDVV; d += 4) {
            a0 += wrow[d]     * rr[2*d];
            a1 += wrow[d + 1] * rr[2*d + 2];
            a2 += wrow[d + 2] * rr[2*d + 4];
            a3 += wrow[d + 3] * rr[2*d + 6];
        }
        g_w2[k * 32 + t] = (a0 + a1) + (a2 + a3);
    }
}

// ---------------- tensor-core GEMM (TF32, 5-stage, fused epilogue) ---------
// A pre-rounded tf32 in gmem. B raw fp32; fragments cvt'd in-loop.
// SEG: 1-D grid; blocks [0,768) are GEMM tiles over {q,k,v,g} with fused
// RoPE/split/transpose epilogues; blocks [768,1280) compute router logits
// rlog = xc @ W2 (hidden in the GEMM tail wave).
#define AP4 20
#define BPAD 136
#define STGF4 (128*AP4 + 16*BPAD)     // floats per stage = 4736
#define SMEM_GEMM5 (5 * STGF4 * 4)    // 94720 bytes (also >= 128*129*4 staging)
#define GEMM1_BLKS (NCAT/128 * LL/128)   // 768
#define RLOG_BLKS  (LL/4)                // 512

template<bool SEG>
__global__ __launch_bounds__(256, 2) void gemm_tc(
        const float* __restrict__ A,
        const float* __restrict__ B0,
        const float* __restrict__ B1,
        const float* __restrict__ B2,
        const float* __restrict__ B3,
        float* __restrict__ C,
        int N, int K, int silu_ncols) {
    extern __shared__ float sm[];

    int tid = threadIdx.x, lane = tid & 31, warp = tid >> 5;

    int bm, bn;
    if (SEG) {
        int b = blockIdx.x;
        if (b >= GEMM1_BLKS) {
            // ---- router logits block: rlog = xc @ W2 (fp32 exact) ----
            int rb   = b - GEMM1_BLKS;
            int lsub = tid >> 6;            // 0..3
            int u    = tid & 63;
            int hr   = u & 31;
            int kh   = u >> 5;              // k-half 0/1
            int l    = rb * 4 + lsub;
            const float* xrow = g_xc + (size_t)l * DD + kh * 1024;
            const float* w2p  = g_w2 + (size_t)kh * 1024 * 32 + hr;
            float a0 = 0.f, a1 = 0.f, a2 = 0.f, a3 = 0.f;
            #pragma unroll 8
            for (int k = 0; k < 1024; k += 4) {
                a0 += xrow[k]     * w2p[(k    ) * 32];
                a1 += xrow[k + 1] * w2p[(k + 1) * 32];
                a2 += xrow[k + 2] * w2p[(k + 2) * 32];
                a3 += xrow[k + 3] * w2p[(k + 3) * 32];
            }
            float* part = sm;
            part[tid] = (a0 + a1) + (a2 + a3);
            __syncthreads();
            if (kh == 0)
                g_rlog[l * 32 + hr] = part[tid] + part[tid + 32];
            return;
        }
        bn = (b % (NCAT/128)) * 128;
        bm = (b / (NCAT/128)) * 128;
    } else {
        bn = blockIdx.x * 128;
        bm = blockIdx.y * 128;
    }

    int wm = (warp >> 2) * 64, wn = (warp & 3) * 32;
    int g = lane >> 2, t = lane & 3;

    const float* Bseg; int ldb, bcol;
    if (SEG) {
        if (bn < 1024)      { Bseg = B0; ldb = 1024; bcol = bn; }
        else if (bn < 2048) { Bseg = B1; ldb = 1024; bcol = bn - 1024; }
        else if (bn < 4096) { Bseg = B2; ldb = 2048; bcol = bn - 2048; }
        else                { Bseg = B3; ldb = 2048; bcol = bn - 4096; }
    } else {
        Bseg = B0; ldb = N; bcol = bn;
    }

    float acc[4][4][4];
    #pragma unroll
    for (int i = 0; i < 4; i++)
        #pragma unroll
        for (int j = 0; j < 4; j++)
            #pragma unroll
            for (int r = 0; r < 4; r++) acc[i][j][r] = 0.f;

    const float* agp[2];
    const float* bgp[2];
    int asp[2], bsp[2];
    #pragma unroll
    for (int i = 0; i < 2; i++) {
        int idx = tid + i * 256;
        int ar = idx >> 2, ac = (idx & 3) * 4;    // A: 128 rows x 16 k
        int br = idx >> 5, bc = (idx & 31) * 4;   // B: 16 k x 128 cols
        agp[i] = A + (size_t)(bm + ar) * K + ac;
        bgp[i] = Bseg + (size_t)br * ldb + bcol + bc;
        asp[i] = ar * AP4 + ac;
        bsp[i] = 128 * AP4 + br * BPAD + bc;
    }

#define LOAD_STAGE(s, k0) do {                                          \
        float* base_ = sm + (s) * STGF4;                                \
        _Pragma("unroll")                                               \
        for (int i_ = 0; i_ < 2; i_++) {                                \
            cp16(base_ + asp[i_], agp[i_] + (k0));                      \
            cp16(base_ + bsp[i_], bgp[i_] + (size_t)(k0) * ldb);        \
        }                                                               \
        asm volatile("cp.async.commit_group;\n" ::);                    \
    } while (0)

    int nk = K >> 4;                  // K-tile 16
    LOAD_STAGE(0, 0);
    LOAD_STAGE(1, 16);
    LOAD_STAGE(2, 32);
    LOAD_STAGE(3, 48);

    int s = 0;
    for (int kt = 0; kt < nk; kt++) {
        int rem = nk - 1 - kt;
        if (rem >= 3)      asm volatile("cp.async.wait_group 3;\n" ::);
        else if (rem == 2) asm volatile("cp.async.wait_group 2;\n" ::);
        else if (rem == 1) asm volatile("cp.async.wait_group 1;\n" ::);
        else               asm volatile("cp.async.wait_group 0;\n" ::);
        __syncthreads();              // also guarantees kt-1 readers done
        const float* Ah = sm + s * STGF4;
        const float* Bh = Ah + 128 * AP4;

        #pragma unroll
        for (int ko = 0; ko < 16; ko += 8) {
            unsigned af[4][4], bf[4][2];
            #pragma unroll
            for (int fm = 0; fm < 4; fm++) {
                int r0 = wm + fm * 16 + g;
                af[fm][0] = __float_as_uint(Ah[ r0      * AP4 + ko + t]);
                af[fm][1] = __float_as_uint(Ah[(r0 + 8) * AP4 + ko + t]);
                af[fm][2] = __float_as_uint(Ah[ r0      * AP4 + ko + t + 4]);
                af[fm][3] = __float_as_uint(Ah[(r0 + 8) * AP4 + ko + t + 4]);
            }
            #pragma unroll
            for (int fn = 0; fn < 4; fn++) {
                int c0 = wn + fn * 8 + g;
                bf[fn][0] = f2tf(Bh[(ko + t    ) * BPAD + c0]);
                bf[fn][1] = f2tf(Bh[(ko + t + 4) * BPAD + c0]);
            }
            #pragma unroll
            for (int fm = 0; fm < 4; fm++)
                #pragma unroll
                for (int fn = 0; fn < 4; fn++)
                    mma8(acc[fm][fn], af[fm][0], af[fm][1], af[fm][2], af[fm][3],
                         bf[fn][0], bf[fn][1]);
        }
        if (kt + 4 < nk) LOAD_STAGE((kt + 4) % 5, (kt + 4) * 16);
        s = (s == 4) ? 0 : s + 1;
    }

    if (SEG && bn < 4096) {
        // -------- fused epilogue: stage tile, then RoPE/split or transpose --
        __syncthreads();              // all smem reads done; 0 cp.async pending
        float* st = sm;               // [128][129]
        #pragma unroll
        for (int fm = 0; fm < 4; fm++) {
            int r0 = wm + fm * 16 + g;
            #pragma unroll
            for (int fn = 0; fn < 4; fn++) {
                int c0 = wn + fn * 8 + 2 * t;
                float v0 = acc[fm][fn][0], v1 = acc[fm][fn][1];
                float v2 = acc[fm][fn][2], v3 = acc[fm][fn][3];
                if (bn < silu_ncols) {            // whole tile is q
                    v0 = silu_f(v0); v1 = silu_f(v1);
                    v2 = silu_f(v2); v3 = silu_f(v3);
                }
                st[ r0      * 129 + c0] = v0;  st[ r0      * 129 + c0 + 1] = v1;
                st[(r0 + 8) * 129 + c0] = v2;  st[(r0 + 8) * 129 + c0 + 1] = v3;
            }
        }
        __syncthreads();

        if (bn < 2048) {
            // ---- q/k tile: RoPE + bf16 hi/lo split, head-major ----
            bool isq = bn < 1024;
            int h0 = (isq ? bn : bn - 1024) >> 6;
            __nv_bfloat16* Oh = isq ? g_qh : g_kh;
            __nv_bfloat16* Ol = isq ? g_ql : g_kl;
            int u  = tid & 63, hh = u >> 5, i = u & 31;
            int lb = tid >> 6;        // 0..3
            float invf = powf(10000.f, -(float)i / 32.f);
            for (int pass = 0; pass < 32; pass++) {
                int l = lb + pass * 4;
                float x1 = st[l * 129 + hh * 64 + i];
                float x2 = st[l * 129 + hh * 64 + 32 + i];
                float ang = (float)(bm + l) * invf;
                float cc = cosf(ang), ss = sinf(ang);
                float ra = x1 * cc - x2 * ss;
                float rb = x2 * cc + x1 * ss;
                size_t ob = ((size_t)(h0 + hh) * LL + bm + l) * HDKK;
                __nv_bfloat16 hb;
                hb = __float2bfloat16_rn(ra);
                Oh[ob + i] = hb;
                Ol[ob + i] = __float2bfloat16_rn(ra - __bfloat162float(hb));
                hb = __float2bfloat16_rn(rb);
                Oh[ob + 32 + i] = hb;
                Ol[ob + 32 + i] = __float2bfloat16_rn(rb - __bfloat162float(hb));
            }
        } else {
            // ---- v tile (one full head): transpose + bf16 split, [h][c][l] --
            int h = (bn - 2048) >> 7;
            int c = tid >> 1;
            int l0off = (tid & 1) * 64;
            size_t ob = ((size_t)h * HDVV + c) * LL + bm + l0off;
            #pragma unroll
            for (int j = 0; j < 8; j++) {
                unsigned hw[4], lw[4];
                #pragma unroll
                for (int e = 0; e < 4; e++) {
                    int l = l0off + j * 8 + e * 2;
                    float v0 = st[ l      * 129 + c];
                    float v1 = st[(l + 1) * 129 + c];
                    unsigned h0b, l0b, h1b, l1b;
                    split_bf(v0, h0b, l0b);
                    split_bf(v1, h1b, l1b);
                    hw[e] = h0b | (h1b << 16);
                    lw[e] = l0b | (l1b << 16);
                }
                *(uint4*)(g_vth + ob + j * 8) = make_uint4(hw[0], hw[1], hw[2], hw[3]);
                *(uint4*)(g_vtl + ob + j * 8) = make_uint4(lw[0], lw[1], lw[2], lw[3]);
            }
        }
    } else {
        // -------- plain epilogue (g tiles, and gemm2) --------
        #pragma unroll
        for (int fm = 0; fm < 4; fm++) {
            int r0 = bm + wm + fm * 16 + g;
            #pragma unroll
            for (int fn = 0; fn < 4; fn++) {
                int c0 = bn + wn + fn * 8 + 2 * t;
                float v0 = acc[fm][fn][0], v1 = acc[fm][fn][1];
                float v2 = acc[fm][fn][2], v3 = acc[fm][fn][3];
                if (c0 < silu_ncols) {
                    v0 = silu_f(v0); v1 = silu_f(v1);
                    v2 = silu_f(v2); v3 = silu_f(v3);
                }
                *(float2*)(C + (size_t)r0 * N + c0)       = make_float2(v0, v1);
                *(float2*)(C + (size_t)(r0 + 8) * N + c0) = make_float2(v2, v3);
            }
        }
    }
#undef LOAD_STAGE
}

// ---------------- stage 4: router decision + parallel count scan -----------
__global__ void router_kernel() {
    int h = blockIdx.x;                    // 16 blocks, 256 threads
    int tid = threadIdx.x;
    __shared__ float s_score[LL];
    __shared__ unsigned char s_sel[LL];
    __shared__ int ps0[256], ps1[256];
    for (int l = tid; l < LL; l += 256) {
        float z0 = g_rlog[l * 32 + h * 2 + 0];
        float z1 = g_rlog[l * 32 + h * 2 + 1];
        int sel = (z1 > z0) ? 1 : 0;
        float m = fmaxf(z0, z1);
        float e0 = expf(z0 - m), e1 = expf(z1 - m);
        s_sel[l]   = (unsigned char)sel;
        s_score[l] = ((sel == 0) ? e0 : e1) / (e0 + e1);
    }
    __syncthreads();
    int base = tid * 8;
    int c0 = 0, c1 = 0;
    #pragma unroll
    for (int i = 0; i < 8; i++) {
        if (s_sel[base + i]) c1++; else c0++;
    }
    ps0[tid] = c0; ps1[tid] = c1;
    __syncthreads();
    for (int off = 1; off < 256; off <<= 1) {
        int v0 = (tid >= off) ? ps0[tid - off] : 0;
        int v1 = (tid >= off) ? ps1[tid - off] : 0;
        __syncthreads();
        ps0[tid] += v0; ps1[tid] += v1;
        __syncthreads();
    }
    int b0 = ps0[tid] - c0, b1 = ps1[tid] - c1;   // exclusive prefix
    const float scale = 0.125f;                   // HDK^{-1/2}
    #pragma unroll
    for (int i = 0; i < 8; i++) {
        int l = base + i;
        int sel = s_sel[l];
        int cnt;
        if (sel) { b1++; cnt = b1; } else { b0++; cnt = b0; }
        g_rsel[h * LL + l] = sel;
        g_coef[h * LL + l] = s_score[l] / (float)cnt * scale;
    }
}

// ---------------- stage 5: bf16 attention, Q in registers ------------------
#define SU 36
#define AKB 0
#define AKSTG (2*64*SU)              // one K stage = hi + lo
#define ASH (AKB + 2*AKSTG)
#define ASL (ASH + 64*SU)
#define AVH (ASL + 64*SU)            // V^T: 128 rows
#define AVL (AVH + 128*SU)
#define ACF (AVL + 128*SU)
#define ARR (ACF + 64)
#define ARC (ARR + 64)
#define ATTN5_WORDS (ARC + 64)
#define ATTN5_BYTES (ATTN5_WORDS * 4)   // ~93 KB -> 2 CTAs/SM

__global__ __launch_bounds__(256, 2) void attn_tc() {
    extern __shared__ unsigned smu[];
    unsigned* Sh = smu + ASH;  unsigned* Sl = smu + ASL;
    unsigned* Vh = smu + AVH;  unsigned* Vl = smu + AVL;
    float* coef_r = (float*)(smu + ACF);
    int*   rsel_r = (int*)(smu + ARR);
    int*   rsel_c = (int*)(smu + ARC);

    int h   = blockIdx.y;
    int l0  = (gridDim.x - 1 - blockIdx.x) * 64;   // heavy tiles first
    int tid = threadIdx.x, lane = tid & 31, warp = tid >> 5;
    int g = lane >> 2, t = lane & 3;
    int wm  = (warp >> 1) * 16;
    int wns = (warp & 1) * 32;
    int wno = (warp & 1) * 64;

    const __nv_bfloat16* Kh_g  = g_kh  + (size_t)h * LL * HDKK;
    const __nv_bfloat16* Kl_g  = g_kl  + (size_t)h * LL * HDKK;
    const __nv_bfloat16* Vth_g = g_vth + (size_t)h * HDVV * LL;
    const __nv_bfloat16* Vtl_g = g_vtl + (size_t)h * HDVV * LL;

#define LOAD_K(s, m0) do {                                                  \
        unsigned* kh_ = smu + AKB + (s) * AKSTG;                            \
        unsigned* kl_ = kh_ + 64*SU;                                        \
        _Pragma("unroll")                                                   \
        for (int i_ = 0; i_ < 2; i_++) {                                    \
            int idx_ = tid + i_ * 256, r_ = idx_ >> 3, j_ = idx_ & 7;       \
            cp16b(kh_ + r_*SU + j_*4, Kh_g + (size_t)((m0)+r_)*HDKK + j_*8);\
            cp16b(kl_ + r_*SU + j_*4, Kl_g + (size_t)((m0)+r_)*HDKK + j_*8);\
        }                                                                   \
        asm volatile("cp.async.commit_group;\n" ::);                        \
    } while (0)

#define LOAD_V(m0) do {                                                     \
        _Pragma("unroll")                                                   \
        for (int i_ = 0; i_ < 4; i_++) {                                    \
            int idx_ = tid + i_ * 256, r_ = idx_ >> 3, j_ = idx_ & 7;       \
            cp16b(Vh + r_*SU + j_*4, Vth_g + (size_t)r_*LL + (m0) + j_*8);  \
            cp16b(Vl + r_*SU + j_*4, Vtl_g + (size_t)r_*LL + (m0) + j_*8);  \
        }                                                                   \
        asm volatile("cp.async.commit_group;\n" ::);                        \
    } while (0)

    // prologue: K(0) in flight; Q fragments -> registers (reused all tiles)
    LOAD_K(0, 0);
    unsigned qh_r[4][4], ql_r[4][4];
    {
        const unsigned* Qg_h = (const unsigned*)g_qh + ((size_t)h * LL + l0) * 32;
        const unsigned* Qg_l = (const unsigned*)g_ql + ((size_t)h * LL + l0) * 32;
        int r0 = wm + g;
        #pragma unroll
        for (int kk = 0; kk < 4; kk++) {
            int w0 = kk * 8 + t, w1 = w0 + 4;
            qh_r[kk][0] = Qg_h[ r0      * 32 + w0];
            qh_r[kk][1] = Qg_h[(r0 + 8) * 32 + w0];
            qh_r[kk][2] = Qg_h[ r0      * 32 + w1];
            qh_r[kk][3] = Qg_h[(r0 + 8) * 32 + w1];
            ql_r[kk][0] = Qg_l[ r0      * 32 + w0];
            ql_r[kk][1] = Qg_l[(r0 + 8) * 32 + w0];
            ql_r[kk][2] = Qg_l[ r0      * 32 + w1];
            ql_r[kk][3] = Qg_l[(r0 + 8) * 32 + w1];
        }
    }
    if (tid < 64) {
        rsel_r[tid] = g_rsel[h * LL + l0 + tid];
        coef_r[tid] = g_coef[h * LL + l0 + tid];
    }

    float acc_o[8][4];
    #pragma unroll
    for (int fn = 0; fn < 8; fn++)
        #pragma unroll
        for (int r = 0; r < 4; r++) acc_o[fn][r] = 0.f;

    int ntiles = (l0 >> 6) + 1;
    for (int mt = 0; mt < ntiles; mt++) {
        int m0 = mt * 64;
        int s  = mt & 1;
        __syncthreads();                    // prev V/S reads done
        LOAD_V(m0);
        if (tid < 64) rsel_c[tid] = g_rsel[h * LL + m0 + tid];
        asm volatile("cp.async.wait_group 1;\n" ::);   // K(mt) done
        __syncthreads();

        const unsigned* Kts = smu + AKB + s * AKSTG;
        const unsigned* Kls = Kts + 64*SU;

        // ---- QK^T (bf16 3-term): warp tile 16x32, 4 k16 steps ----
        float acc_s[4][4];
        #pragma unroll
        for (int fn = 0; fn < 4; fn++)
            #pragma unroll
            for (int r = 0; r < 4; r++) acc_s[fn][r] = 0.f;

        #pragma unroll
        for (int kk = 0; kk < 4; kk++) {
            int p0 = kk * 8;
            #pragma unroll
            for (int fn = 0; fn < 4; fn++) {
                int c0 = wns + fn * 8 + g;
                unsigned bh0 = Kts[c0 * SU + p0 + t];
                unsigned bh1 = Kts[c0 * SU + p0 + t + 4];
                unsigned bl0 = Kls[c0 * SU + p0 + t];
                unsigned bl1 = Kls[c0 * SU + p0 + t + 4];
                mma16(acc_s[fn], qh_r[kk][0], qh_r[kk][1], qh_r[kk][2], qh_r[kk][3], bh0, bh1);
                mma16(acc_s[fn], qh_r[kk][0], qh_r[kk][1], qh_r[kk][2], qh_r[kk][3], bl0, bl1);
                mma16(acc_s[fn], ql_r[kk][0], ql_r[kk][1], ql_r[kk][2], ql_r[kk][3], bh0, bh1);
            }
        }

        // prefetch K(mt+1) — K(mt) reads are done
        if (mt + 1 < ntiles) LOAD_K(s ^ 1, m0 + 64);

        // ---- mask + coef, pack bf16 hi/lo pairs into S ----
        {
            int r0 = wm + g, r1 = r0 + 8;
            int gl0 = l0 + r0, gl1 = l0 + r1;
            int e0 = rsel_r[r0], e1 = rsel_r[r1];
            float cf0 = coef_r[r0], cf1 = coef_r[r1];
            #pragma unroll
            for (int fn = 0; fn < 4; fn++) {
                int c = wns + fn * 8 + 2 * t;
                int gm0 = m0 + c, gm1 = gm0 + 1;
                int ec0 = rsel_c[c], ec1 = rsel_c[c + 1];
                float s00 = (gm0 <= gl0 && ec0 == e0) ? acc_s[fn][0] * cf0 : 0.f;
                float s01 = (gm1 <= gl0 && ec1 == e0) ? acc_s[fn][1] * cf0 : 0.f;
                float s10 = (gm0 <= gl1 && ec0 == e1) ? acc_s[fn][2] * cf1 : 0.f;
                float s11 = (gm1 <= gl1 && ec1 == e1) ? acc_s[fn][3] * cf1 : 0.f;
                unsigned h00, l00, h01, l01, h10, l10, h11, l11;
                split_bf(s00, h00, l00); split_bf(s01, h01, l01);
                split_bf(s10, h10, l10); split_bf(s11, h11, l11);
                int pi = (wns >> 1) + fn * 4 + t;
                Sh[r0 * SU + pi] = h00 | (h01 << 16);
                Sl[r0 * SU + pi] = l00 | (l01 << 16);
                Sh[r1 * SU + pi] = h10 | (h11 << 16);
                Sl[r1 * SU + pi] = l10 | (l11 << 16);
            }
        }
        if (mt + 1 < ntiles)
            asm volatile("cp.async.wait_group 1;\n" ::);  // V(mt) done, K(mt+1) pending
        else
            asm volatile("cp.async.wait_group 0;\n" ::);  // last tile: V must be done
        __syncthreads();                                   // S + V visible

        // ---- O += S @ V (bf16 3-term): warp tile 16x64, 4 k16 steps ----
        #pragma unroll
        for (int kk = 0; kk < 4; kk++) {
            int p0 = kk * 8;
            int r0 = wm + g;
            unsigned ah0 = Sh[ r0      * SU + p0 + t];
            unsigned ah1 = Sh[(r0 + 8) * SU + p0 + t];
            unsigned ah2 = Sh[ r0      * SU + p0 + t + 4];
            unsigned ah3 = Sh[(r0 + 8) * SU + p0 + t + 4];
            unsigned al0 = Sl[ r0      * SU + p0 + t];
            unsigned al1 = Sl[(r0 + 8) * SU + p0 + t];
            unsigned al2 = Sl[ r0      * SU + p0 + t + 4];
            unsigned al3 = Sl[(r0 + 8) * SU + p0 + t + 4];
            #pragma unroll
            for (int fn = 0; fn < 8; fn++) {
                int c0 = wno + fn * 8 + g;
                unsigned bh0 = Vh[c0 * SU + p0 + t];
                unsigned bh1 = Vh[c0 * SU + p0 + t + 4];
                unsigned bl0 = Vl[c0 * SU + p0 + t];
                unsigned bl1 = Vl[c0 * SU + p0 + t + 4];
                mma16(acc_o[fn], ah0, ah1, ah2, ah3, bh0, bh1);
                mma16(acc_o[fn], ah0, ah1, ah2, ah3, bl0, bl1);
                mma16(acc_o[fn], al0, al1, al2, al3, bh0, bh1);
            }
        }
    }

    // ---- fused LayerNorm(128) * silu(gate) epilogue ----
    __syncthreads();                          // all smem reads done; reuse Sh region
    float* red_s = (float*)(smu + ASH);       // [128]: half*64 + row
    float* red_q = red_s + 128;               // [128]
    {
        int half = warp & 1;
        int r0 = wm + g, r1 = r0 + 8;
        float s0 = 0.f, q0 = 0.f, s1 = 0.f, q1 = 0.f;
        #pragma unroll
        for (int fn = 0; fn < 8; fn++) {
            float v0 = acc_o[fn][0], v1 = acc_o[fn][1];
            float v2 = acc_o[fn][2], v3 = acc_o[fn][3];
            s0 += v0 + v1;  q0 += v0*v0 + v1*v1;
            s1 += v2 + v3;  q1 += v2*v2 + v3*v3;
        }
        #pragma unroll
        for (int off = 1; off <= 2; off <<= 1) {
            s0 += __shfl_xor_sync(0xffffffffu, s0, off);
            q0 += __shfl_xor_sync(0xffffffffu, q0, off);
            s1 += __shfl_xor_sync(0xffffffffu, s1, off);
            q1 += __shfl_xor_sync(0xffffffffu, q1, off);
        }
        if (t == 0) {
            red_s[half*64 + r0] = s0;  red_q[half*64 + r0] = q0;
            red_s[half*64 + r1] = s1;  red_q[half*64 + r1] = q1;
        }
        __syncthreads();
        float S0 = red_s[r0] + red_s[64 + r0];
        float Q0 = red_q[r0] + red_q[64 + r0];
        float S1 = red_s[r1] + red_s[64 + r1];
        float Q1 = red_q[r1] + red_q[64 + r1];
        float mu0 = S0 * (1.f/128.f), mu1 = S1 * (1.f/128.f);
        float inv0 = rsqrtf(Q0 * (1.f/128.f) - mu0*mu0 + 1e-5f);
        float inv1 = rsqrtf(Q1 * (1.f/128.f) - mu1*mu1 + 1e-5f);
        size_t gbase0 = (size_t)(l0 + r0) * NCAT + 2*DKK + DVV + h * HDVV;
        size_t gbase1 = (size_t)(l0 + r1) * NCAT + 2*DKK + DVV + h * HDVV;
        size_t ybase0 = (size_t)(l0 + r0) * DVV + h * HDVV;
        size_t ybase1 = (size_t)(l0 + r1) * DVV + h * HDVV;
        #pragma unroll
        for (int fn = 0; fn < 8; fn++) {
            int c = wno + fn * 8 + 2 * t;
            float2 gt0 = *(const float2*)(g_qkvg + gbase0 + c);
            float2 gt1 = *(const float2*)(g_qkvg + gbase1 + c);
            float2 y0, y1;
            y0.x = tf32r(silu_f(gt0.x) * (acc_o[fn][0] - mu0) * inv0);
            y0.y = tf32r(silu_f(gt0.y) * (acc_o[fn][1] - mu0) * inv0);
            y1.x = tf32r(silu_f(gt1.x) * (acc_o[fn][2] - mu1) * inv1);
            y1.y = tf32r(silu_f(gt1.y) * (acc_o[fn][3] - mu1) * inv1);
            *(float2*)(g_y + ybase0 + c) = y0;
            *(float2*)(g_y + ybase1 + c) = y1;
        }
    }
}

// ---------------- launch ----------------------------------------------------
extern "C" void kernel_launch(void* const* d_in, const int* in_sizes, int n_in,
                              void* d_out, int out_size) {
    const float* x    = (const float*)d_in[0];
    const float* cw   = (const float*)d_in[1];
    const float* Wq   = (const float*)d_in[2];
    const float* Wk   = (const float*)d_in[3];
    const float* Wv   = (const float*)d_in[4];
    const float* Wg   = (const float*)d_in[5];
    const float* rw   = (const float*)d_in[6];
    const float* Wout = (const float*)d_in[7];
    float* out = (float*)d_out;

    float *p_xctf, *p_qkvg, *p_y;
    cudaGetSymbolAddress((void**)&p_xctf, g_xctf);
    cudaGetSymbolAddress((void**)&p_qkvg, g_qkvg);
    cudaGetSymbolAddress((void**)&p_y,    g_y);

    cudaFuncSetAttribute(attn_tc,
                         cudaFuncAttributeMaxDynamicSharedMemorySize, ATTN5_BYTES);
    cudaFuncSetAttribute(gemm_tc<true>,
                         cudaFuncAttributeMaxDynamicSharedMemorySize, SMEM_GEMM5);
    cudaFuncSetAttribute(gemm_tc<false>,
                         cudaFuncAttributeMaxDynamicSharedMemorySize, SMEM_GEMM5);

    // conv + silu, with W2 blocks riding along
    conv_silu_kernel<<<CONV_BLKS + DD/8, 256>>>(x, cw, Wv, rw);

    // fused QKVG projection (epilogue does silu(q)+RoPE+split, v transpose+split)
    // + router-logit blocks hidden in the tail wave
    gemm_tc<true><<<GEMM1_BLKS + RLOG_BLKS, 256, SMEM_GEMM5>>>(
        p_xctf, Wq, Wk, Wv, Wg, p_qkvg, NCAT, DD, DKK);

    router_kernel<<<HH, 256>>>();

    attn_tc<<<dim3(LL/64, HH), 256, ATTN5_BYTES>>>();

    gemm_tc<false><<<dim3(DD/128, LL/128), 256, SMEM_GEMM5>>>(
        p_y, Wout, Wout, Wout, Wout, out, DD, DVV, 0);
}